// round 13
// baseline (speedup 1.0000x reference)
#include <cuda_runtime.h>
#include <cuda_bf16.h>
#include <math.h>
#include <stdint.h>

// Problem constants
#define N_TOKENS 131072
#define E_DIM    128
#define KCODES   1024
#define NUM_Q    4
#define MTILE    128                 // tokens per CTA
#define NTILE    128                 // codes per N-tile
#define N_NT     (KCODES / NTILE)    // 8
#define CAND_CAP 8
#define MARGIN   1.5e-3f
#define SK_B     272                 // smem row stride bytes (128 bf16 + 16B pad)

// SMEM byte offsets
#define SM_A     0                   // 128*272 = 34816
#define SM_B0    34816
#define SM_B1    69632
#define SM_NORM  104448              // 1024 f32
#define SM_ATOK  108544              // 128 f32
#define SM_CNT   109056              // 128 i32
#define SM_TOTAL 110080              // 107.5 KB -> 2 CTAs/SM

// ---------------- device globals (no allocations allowed) ----------------
__device__ double g_loss;
__device__ float  g_cbnorm[NUM_Q * KCODES];
__device__ float  g_Rcur[(size_t)N_TOKENS * E_DIM];
__device__ __nv_bfloat16 g_Cb[(size_t)NUM_Q * KCODES * E_DIM];   // bf16(cb)
__device__ unsigned short g_cand[(size_t)N_TOKENS * CAND_CAP];
__device__ int g_ovfcnt[NUM_Q];
__device__ int g_ovftok[NUM_Q][N_TOKENS];

// ---------------- PTX helpers (sm_80+-portable; no tcgen05!) ----------------
__device__ __forceinline__ uint32_t smem_u32(const void* p) {
    uint32_t a;
    asm("{ .reg .u64 t; cvta.to.shared.u64 t, %1; cvt.u32.u64 %0, t; }"
        : "=r"(a) : "l"(p));
    return a;
}
#define CP_ASYNC16(sa, ga) \
    asm volatile("cp.async.cg.shared.global [%0], [%1], 16;" :: "r"(sa), "l"(ga))
#define CP_COMMIT() asm volatile("cp.async.commit_group;" ::: "memory")
#define CP_WAIT0()  asm volatile("cp.async.wait_group 0;" ::: "memory")
#define LDMATRIX_X4(r0, r1, r2, r3, addr) \
    asm volatile("ldmatrix.sync.aligned.m8n8.x4.shared.b16 {%0,%1,%2,%3}, [%4];" \
                 : "=r"(r0), "=r"(r1), "=r"(r2), "=r"(r3) : "r"(addr))
#define MMA_BF16(c, a, b0v, b1v) \
    asm volatile("mma.sync.aligned.m16n8k16.row.col.f32.bf16.bf16.f32 " \
                 "{%0,%1,%2,%3}, {%4,%5,%6,%7}, {%8,%9}, {%0,%1,%2,%3};" \
                 : "+f"((c)[0]), "+f"((c)[1]), "+f"((c)[2]), "+f"((c)[3]) \
                 : "r"((a)[0]), "r"((a)[1]), "r"((a)[2]), "r"((a)[3]), \
                   "r"(b0v), "r"(b1v))

// ---------------- proven numeric contracts (DO NOT TOUCH) ----------------
__device__ __forceinline__ float rowsumsq_xla_gpu(const float* v) {
    float part[32];
#pragma unroll
    for (int l = 0; l < 32; l++) {
        float a = __fmul_rn(v[l], v[l]);
        a = __fadd_rn(a, __fmul_rn(v[l + 32], v[l + 32]));
        a = __fadd_rn(a, __fmul_rn(v[l + 64], v[l + 64]));
        a = __fadd_rn(a, __fmul_rn(v[l + 96], v[l + 96]));
        part[l] = a;
    }
#pragma unroll
    for (int off = 16; off > 0; off >>= 1)
#pragma unroll
        for (int l = 0; l < 16; l++)
            if (l < off) part[l] = __fadd_rn(part[l], part[l + off]);
    return part[0];
}
// Exact B dot: sequential fused FMA ascending e.
// r uses PLAIN loads (callers pass global OR shared pointers — generic ld);
// cb is always global, so __ldg is safe there.
__device__ __forceinline__ float dot_seq(const float* __restrict__ r,
                                         const float* __restrict__ cb) {
    float acc = 0.0f;
#pragma unroll
    for (int i = 0; i < E_DIM / 4; i++) {
        float4 c = __ldg((const float4*)cb + i);
        float4 rv = ((const float4*)r)[i];
        acc = fmaf(rv.x, c.x, acc);
        acc = fmaf(rv.y, c.y, acc);
        acc = fmaf(rv.z, c.z, acc);
        acc = fmaf(rv.w, c.w, acc);
    }
    return acc;
}

// Straight-through epilogue for one float4 block (proven bit-exact path)
__device__ __forceinline__ void st_epilogue_elem(
    int token, int q, int i, float4 rv, const float4* qrow,
    float* out, float& lossAcc)
{
    float4 qv = __ldg(&qrow[i]);
    float4 qz, rn, xv;
    qz.x = __fadd_rn(rv.x, __fsub_rn(qv.x, rv.x));
    qz.y = __fadd_rn(rv.y, __fsub_rn(qv.y, rv.y));
    qz.z = __fadd_rn(rv.z, __fsub_rn(qv.z, rv.z));
    qz.w = __fadd_rn(rv.w, __fsub_rn(qv.w, rv.w));
    rn.x = __fsub_rn(rv.x, qz.x);
    rn.y = __fsub_rn(rv.y, qz.y);
    rn.z = __fsub_rn(rv.z, qz.z);
    rn.w = __fsub_rn(rv.w, qz.w);
    lossAcc = __fadd_rn(lossAcc, __fmul_rn(rn.x, rn.x));
    lossAcc = __fadd_rn(lossAcc, __fmul_rn(rn.y, rn.y));
    lossAcc = __fadd_rn(lossAcc, __fmul_rn(rn.z, rn.z));
    lossAcc = __fadd_rn(lossAcc, __fmul_rn(rn.w, rn.w));
    float4* xqrow = (float4*)(out + (size_t)token * E_DIM);
    if (q == 0) {
        xv = qz;
    } else {
        xv = xqrow[i];
        xv.x = __fadd_rn(xv.x, qz.x);
        xv.y = __fadd_rn(xv.y, qz.y);
        xv.z = __fadd_rn(xv.z, qz.z);
        xv.w = __fadd_rn(xv.w, qz.w);
    }
    xqrow[i] = xv;
    if (q < NUM_Q - 1)
        ((float4*)(g_Rcur + (size_t)token * E_DIM))[i] = rn;
}

// ---------------- kernels ----------------
__global__ void prepA_kernel(const float* __restrict__ cbs) {
    int i = blockIdx.x * blockDim.x + threadIdx.x;
    if (i == 0) {
        g_loss = 0.0;
#pragma unroll
        for (int s = 0; s < NUM_Q; s++) g_ovfcnt[s] = 0;
    }
    if (i >= NUM_Q * KCODES) return;
    const float* row = cbs + (size_t)i * E_DIM;
    float v[E_DIM];
#pragma unroll 8
    for (int e = 0; e < E_DIM; e++) v[e] = __ldg(&row[e]);
    g_cbnorm[i] = rowsumsq_xla_gpu(v);
}
__global__ void prepB_kernel(const float* __restrict__ cbs) {
    int i = blockIdx.x * blockDim.x + threadIdx.x;
    if (i < NUM_Q * KCODES * E_DIM)
        g_Cb[i] = __float2bfloat16(__ldg(&cbs[i]));
}

// Fused stage kernel: bf16 mma.sync filter + exact rescore + straight-through
__global__ void __launch_bounds__(256, 2)
stage_kernel(const float* __restrict__ x, const float* __restrict__ cbs,
             float* __restrict__ out, int q)
{
    extern __shared__ __align__(16) char smem[];
    const uint32_t sb = smem_u32(smem);
    float* snorm = (float*)(smem + SM_NORM);
    float* sAtok = (float*)(smem + SM_ATOK);
    int*   scnt  = (int*)(smem + SM_CNT);

    const int tid  = threadIdx.x;
    const int wid  = tid >> 5;
    const int lane = tid & 31;
    const int tokBase = blockIdx.x * MTILE;
    const float* Rsrc = (q == 0) ? x : g_Rcur;

    if (tid < MTILE) scnt[tid] = 0;
    for (int i = tid; i < KCODES; i += 256) snorm[i] = g_cbnorm[q * KCODES + i];

    // A tile (bf16(r)) + exact Atok (XLA order)
    if (tid < MTILE) {
        float4 Rr[E_DIM / 4];
        const float4* src = (const float4*)(Rsrc + (size_t)(tokBase + tid) * E_DIM);
#pragma unroll
        for (int i = 0; i < E_DIM / 4; i++) Rr[i] = __ldg(&src[i]);
        sAtok[tid] = rowsumsq_xla_gpu((const float*)Rr);
        __nv_bfloat16* arow = (__nv_bfloat16*)(smem + SM_A + tid * SK_B);
        const float* Rf = (const float*)Rr;
#pragma unroll
        for (int e = 0; e < E_DIM; e++) arow[e] = __float2bfloat16(Rf[e]);
    }
    // prefetch B tile 0
    {
        const char* gB = (const char*)&g_Cb[((size_t)q * KCODES) * E_DIM];
        for (int i = tid; i < NTILE * 16; i += 256)
            CP_ASYNC16(sb + SM_B0 + (i >> 4) * SK_B + (i & 15) * 16,
                       gB + (size_t)i * 16);
        CP_COMMIT();
    }
    __syncthreads();

    const int mBase  = (wid & 3) * 32;    // 4 M-strips of 32 rows
    const int nBaseW = (wid >> 2) * 64;   // 2 N-strips of 64 cols

    // Per-thread running row minima (rows fixed per thread across tiles).
    // Sound threshold: runmin >= final min  =>  margin test never misses.
    float rmin[2][2];
#pragma unroll
    for (int mt = 0; mt < 2; mt++)
        rmin[mt][0] = rmin[mt][1] = __int_as_float(0x7f800000);

    for (int nt = 0; nt < N_NT; nt++) {
        CP_WAIT0();
        __syncthreads();
        if (nt + 1 < N_NT) {
            uint32_t sBn = sb + (((nt + 1) & 1) ? SM_B1 : SM_B0);
            const char* gB = (const char*)
                &g_Cb[((size_t)q * KCODES + (nt + 1) * NTILE) * E_DIM];
            for (int i = tid; i < NTILE * 16; i += 256)
                CP_ASYNC16(sBn + (i >> 4) * SK_B + (i & 15) * 16,
                           gB + (size_t)i * 16);
            CP_COMMIT();
        }
        const uint32_t sBc = sb + ((nt & 1) ? SM_B1 : SM_B0);

        float acc[2][8][4];
#pragma unroll
        for (int mt = 0; mt < 2; mt++)
#pragma unroll
            for (int ng = 0; ng < 8; ng++)
#pragma unroll
                for (int j = 0; j < 4; j++) acc[mt][ng][j] = 0.0f;

        const uint32_t aAddr = sb + SM_A
            + (uint32_t)(mBase + (lane & 15)) * SK_B + (uint32_t)(lane >> 4) * 16;
        const uint32_t bAddr = sBc
            + (uint32_t)(nBaseW + ((lane >> 4) << 3) + (lane & 7)) * SK_B
            + (uint32_t)((lane >> 3) & 1) * 16;

#pragma unroll
        for (int k = 0; k < E_DIM / 16; k++) {
            uint32_t a[2][4];
            LDMATRIX_X4(a[0][0], a[0][1], a[0][2], a[0][3], aAddr + k * 32);
            LDMATRIX_X4(a[1][0], a[1][1], a[1][2], a[1][3],
                        aAddr + 16 * SK_B + k * 32);
            uint32_t b[4][4];
#pragma unroll
            for (int g = 0; g < 4; g++)
                LDMATRIX_X4(b[g][0], b[g][1], b[g][2], b[g][3],
                            bAddr + g * 16 * SK_B + k * 32);
#pragma unroll
            for (int mt = 0; mt < 2; mt++)
#pragma unroll
                for (int g = 0; g < 4; g++) {
                    MMA_BF16(acc[mt][2 * g],     a[mt], b[g][0], b[g][1]);
                    MMA_BF16(acc[mt][2 * g + 1], a[mt], b[g][2], b[g][3]);
                }
        }

        // Epilogue: d-hat, quad-combined tile min -> runmin, margin append
#pragma unroll
        for (int mt = 0; mt < 2; mt++) {
            const int r0 = mBase + mt * 16 + (lane >> 2);
            const int r1 = r0 + 8;
            const float A0 = sAtok[r0], A1 = sAtok[r1];
            float m0 = __int_as_float(0x7f800000), m1 = m0;
#pragma unroll
            for (int ng = 0; ng < 8; ng++) {
                const int c = nt * NTILE + nBaseW + ng * 8 + 2 * (lane & 3);
                const float C0 = snorm[c], C1 = snorm[c + 1];
                float d00 = __fadd_rn(__fsub_rn(A0, __fmul_rn(2.0f, acc[mt][ng][0])), C0);
                float d01 = __fadd_rn(__fsub_rn(A0, __fmul_rn(2.0f, acc[mt][ng][1])), C1);
                float d10 = __fadd_rn(__fsub_rn(A1, __fmul_rn(2.0f, acc[mt][ng][2])), C0);
                float d11 = __fadd_rn(__fsub_rn(A1, __fmul_rn(2.0f, acc[mt][ng][3])), C1);
                acc[mt][ng][0] = d00; acc[mt][ng][1] = d01;
                acc[mt][ng][2] = d10; acc[mt][ng][3] = d11;
                m0 = fminf(m0, fminf(d00, d01));
                m1 = fminf(m1, fminf(d10, d11));
            }
            m0 = fminf(m0, __shfl_xor_sync(0xffffffffu, m0, 1));
            m0 = fminf(m0, __shfl_xor_sync(0xffffffffu, m0, 2));
            m1 = fminf(m1, __shfl_xor_sync(0xffffffffu, m1, 1));
            m1 = fminf(m1, __shfl_xor_sync(0xffffffffu, m1, 2));
            rmin[mt][0] = fminf(rmin[mt][0], m0);
            rmin[mt][1] = fminf(rmin[mt][1], m1);
            const float t0 = rmin[mt][0] + MARGIN;
            const float t1 = rmin[mt][1] + MARGIN;
#pragma unroll
            for (int ng = 0; ng < 8; ng++) {
                const int c = nt * NTILE + nBaseW + ng * 8 + 2 * (lane & 3);
#pragma unroll
                for (int j = 0; j < 4; j++) {
                    const float d = acc[mt][ng][j];
                    const float thr = (j < 2) ? t0 : t1;
                    if (d <= thr) {
                        const int row = (j < 2) ? r0 : r1;
                        int pos = atomicAdd(&scnt[row], 1);
                        if (pos < CAND_CAP)
                            g_cand[(size_t)(tokBase + row) * CAND_CAP + pos] =
                                (unsigned short)(c + (j & 1));
                    }
                }
            }
        }
    }
    __syncthreads();   // all appends to scnt/g_cand visible

    // ---- Fused finish: exact rescore + straight-through (token = tid) ----
    float lossAcc = 0.0f;
    if (tid < MTILE) {
        const int token = tokBase + tid;
        const int c = scnt[tid];
        const bool ovf = (c > CAND_CAP || c == 0);
        if (ovf) {
            int pos = atomicAdd(&g_ovfcnt[q], 1);
            g_ovftok[q][pos] = token;
        } else {
            const float* Rg = Rsrc + (size_t)token * E_DIM;
            const float* cb = cbs + (size_t)q * KCODES * E_DIM;
            const float A = sAtok[tid];   // same bits as XLA-order recompute
            float best = __int_as_float(0x7f800000);
            int bestk = 0;
            for (int i = 0; i < c; i++) {
                int k = g_cand[(size_t)token * CAND_CAP + i];
                float b = dot_seq(Rg, cb + (size_t)k * E_DIM);
                float dv = __fadd_rn(__fsub_rn(A, __fmul_rn(2.0f, b)),
                                     snorm[k]);
                if (i == 0 || dv < best || (dv == best && k < bestk)) {
                    best = dv; bestk = k;
                }
            }
            const float4* qrow = (const float4*)(cb + (size_t)bestk * E_DIM);
            const float4* Rg4  = (const float4*)Rg;
#pragma unroll
            for (int i = 0; i < E_DIM / 4; i++)
                st_epilogue_elem(token, q, i, __ldg(&Rg4[i]), qrow, out, lossAcc);
            out[(size_t)N_TOKENS * E_DIM + 1 + (size_t)token * NUM_Q + q] =
                (float)bestk;
        }
    }
    // Loss reduction: warps 0-3 only; ALL 32 lanes participate (ovf => 0)
    if (tid < MTILE) {
#pragma unroll
        for (int o = 16; o > 0; o >>= 1)
            lossAcc += __shfl_xor_sync(0xffffffffu, lossAcc, o);
        if (lane == 0) atomicAdd(&g_loss, (double)lossAcc);
    }
}

// Fallback: warp-per-token exact full scan for overflow tokens (rare)
__global__ void __launch_bounds__(256)
fallback_kernel(const float* __restrict__ x, const float* __restrict__ cbs,
                float* __restrict__ out, int q)
{
    __shared__ __align__(16) float sR[8][E_DIM];
    const int cnt   = g_ovfcnt[q];
    const int wslot = threadIdx.x >> 5;
    const int lane  = threadIdx.x & 31;
    const float* cb = cbs + (size_t)q * KCODES * E_DIM;

    for (int qi = blockIdx.x * 8 + wslot; qi < cnt; qi += gridDim.x * 8) {
        const int token = g_ovftok[q][qi];
        const float* Rsrc = (q == 0) ? x : g_Rcur;
        float4 rv = __ldg((const float4*)(Rsrc + (size_t)token * E_DIM) + lane);
        ((float4*)sR[wslot])[lane] = rv;
        __syncwarp();
        float A = rowsumsq_xla_gpu(sR[wslot]);
        float best = __int_as_float(0x7f800000);
        int bestk = KCODES;
#pragma unroll 1
        for (int j = 0; j < KCODES / 32; j++) {
            int k = lane + j * 32;
            float b = dot_seq(sR[wslot], cb + (size_t)k * E_DIM);
            float dv = __fadd_rn(__fsub_rn(A, __fmul_rn(2.0f, b)),
                                 g_cbnorm[q * KCODES + k]);
            if (dv < best || (dv == best && k < bestk)) { best = dv; bestk = k; }
        }
#pragma unroll
        for (int o = 16; o > 0; o >>= 1) {
            float od = __shfl_down_sync(0xffffffffu, best, o);
            int   ok = __shfl_down_sync(0xffffffffu, bestk, o);
            if (od < best || (od == best && ok < bestk)) { best = od; bestk = ok; }
        }
        bestk = __shfl_sync(0xffffffffu, bestk, 0);

        float lossAcc = 0.0f;
        const float4* qrow = (const float4*)(cb + (size_t)bestk * E_DIM);
        st_epilogue_elem(token, q, lane, rv, qrow, out, lossAcc);
#pragma unroll
        for (int o = 16; o > 0; o >>= 1)
            lossAcc += __shfl_xor_sync(0xffffffffu, lossAcc, o);
        if (lane == 0) {
            out[(size_t)N_TOKENS * E_DIM + 1 + (size_t)token * NUM_Q + q] = (float)bestk;
            atomicAdd(&g_loss, (double)lossAcc);
        }
        __syncwarp();
    }
}

__global__ void finalize_loss_kernel(float* __restrict__ out) {
    double v = g_loss * (0.25 / ((double)NUM_Q * (double)N_TOKENS * (double)E_DIM));
    out[(size_t)N_TOKENS * E_DIM] = (float)v;
}

// ---------------- launch ----------------
extern "C" void kernel_launch(void* const* d_in, const int* in_sizes, int n_in,
                              void* d_out, int out_size)
{
    const float* x   = (const float*)d_in[0];   // [131072, 128]
    const float* cbs = (const float*)d_in[1];   // [4, 1024, 128]
    float* out = (float*)d_out;

    cudaFuncSetAttribute(stage_kernel,
                         cudaFuncAttributeMaxDynamicSharedMemorySize, SM_TOTAL);

    prepA_kernel<<<(NUM_Q * KCODES + 127) / 128, 128>>>(cbs);
    prepB_kernel<<<(NUM_Q * KCODES * E_DIM + 255) / 256, 256>>>(cbs);
    for (int q = 0; q < NUM_Q; q++) {
        stage_kernel<<<N_TOKENS / MTILE, 256, SM_TOTAL>>>(x, cbs, out, q);
        fallback_kernel<<<128, 256>>>(x, cbs, out, q);
    }
    finalize_loss_kernel<<<1, 1>>>(out);
}

// round 14
// speedup vs baseline: 1.0195x; 1.0195x over previous
#include <cuda_runtime.h>
#include <cuda_bf16.h>
#include <math.h>
#include <stdint.h>

// Problem constants
#define N_TOKENS 131072
#define E_DIM    128
#define KCODES   1024
#define NUM_Q    4
#define MTILE    128                 // tokens per CTA
#define NTILE    128                 // codes per N-tile
#define N_NT     (KCODES / NTILE)    // 8
#define CAND_CAP 8
#define MARGIN   1.5e-3f
#define SK_B     272                 // smem row stride bytes (128 bf16 + 16B pad)

// SMEM byte offsets
#define SM_A     0                   // 128*272 = 34816
#define SM_B0    34816
#define SM_B1    69632
#define SM_NORM  104448              // 1024 f32
#define SM_ATOK  108544              // 128 f32
#define SM_CNT   109056              // 128 i32
#define SM_TOTAL 110080              // 107.5 KB -> 2 CTAs/SM

// ---------------- device globals (no allocations allowed) ----------------
__device__ double g_loss;
__device__ float  g_cbnorm[NUM_Q * KCODES];
__device__ float  g_Atok[N_TOKENS];                              // exact A per token
__device__ float  g_Rcur[(size_t)N_TOKENS * E_DIM];
__device__ __nv_bfloat16 g_Cb[(size_t)NUM_Q * KCODES * E_DIM];   // bf16(cb)
__device__ unsigned short g_cand[(size_t)N_TOKENS * CAND_CAP];
__device__ unsigned char  g_candcnt[N_TOKENS];
__device__ int g_ovfcnt[NUM_Q];
__device__ int g_ovftok[NUM_Q][N_TOKENS];

// ---------------- PTX helpers (sm_80+-portable; no tcgen05!) ----------------
__device__ __forceinline__ uint32_t smem_u32(const void* p) {
    uint32_t a;
    asm("{ .reg .u64 t; cvta.to.shared.u64 t, %1; cvt.u32.u64 %0, t; }"
        : "=r"(a) : "l"(p));
    return a;
}
#define CP_ASYNC16(sa, ga) \
    asm volatile("cp.async.cg.shared.global [%0], [%1], 16;" :: "r"(sa), "l"(ga))
#define CP_COMMIT() asm volatile("cp.async.commit_group;" ::: "memory")
#define CP_WAIT0()  asm volatile("cp.async.wait_group 0;" ::: "memory")
#define LDMATRIX_X4(r0, r1, r2, r3, addr) \
    asm volatile("ldmatrix.sync.aligned.m8n8.x4.shared.b16 {%0,%1,%2,%3}, [%4];" \
                 : "=r"(r0), "=r"(r1), "=r"(r2), "=r"(r3) : "r"(addr))
#define MMA_BF16(c, a, b0v, b1v) \
    asm volatile("mma.sync.aligned.m16n8k16.row.col.f32.bf16.bf16.f32 " \
                 "{%0,%1,%2,%3}, {%4,%5,%6,%7}, {%8,%9}, {%0,%1,%2,%3};" \
                 : "+f"((c)[0]), "+f"((c)[1]), "+f"((c)[2]), "+f"((c)[3]) \
                 : "r"((a)[0]), "r"((a)[1]), "r"((a)[2]), "r"((a)[3]), \
                   "r"(b0v), "r"(b1v))

// ---------------- proven numeric contracts (DO NOT TOUCH) ----------------
__device__ __forceinline__ float rowsumsq_xla_gpu(const float* v) {
    float part[32];
#pragma unroll
    for (int l = 0; l < 32; l++) {
        float a = __fmul_rn(v[l], v[l]);
        a = __fadd_rn(a, __fmul_rn(v[l + 32], v[l + 32]));
        a = __fadd_rn(a, __fmul_rn(v[l + 64], v[l + 64]));
        a = __fadd_rn(a, __fmul_rn(v[l + 96], v[l + 96]));
        part[l] = a;
    }
#pragma unroll
    for (int off = 16; off > 0; off >>= 1)
#pragma unroll
        for (int l = 0; l < 16; l++)
            if (l < off) part[l] = __fadd_rn(part[l], part[l + off]);
    return part[0];
}
// Exact B dot: sequential fused FMA ascending e; r via plain generic loads
// (valid for global OR shared pointers); cb always global -> __ldg.
__device__ __forceinline__ float dot_seq(const float* __restrict__ r,
                                         const float* __restrict__ cb) {
    float acc = 0.0f;
#pragma unroll
    for (int i = 0; i < E_DIM / 4; i++) {
        float4 c = __ldg((const float4*)cb + i);
        float4 rv = ((const float4*)r)[i];
        acc = fmaf(rv.x, c.x, acc);
        acc = fmaf(rv.y, c.y, acc);
        acc = fmaf(rv.z, c.z, acc);
        acc = fmaf(rv.w, c.w, acc);
    }
    return acc;
}

// Straight-through epilogue for one float4 block (proven bit-exact path)
__device__ __forceinline__ void st_epilogue_elem(
    int token, int q, int i, float4 rv, const float4* qrow,
    float* out, float& lossAcc)
{
    float4 qv = __ldg(&qrow[i]);
    float4 qz, rn, xv;
    qz.x = __fadd_rn(rv.x, __fsub_rn(qv.x, rv.x));
    qz.y = __fadd_rn(rv.y, __fsub_rn(qv.y, rv.y));
    qz.z = __fadd_rn(rv.z, __fsub_rn(qv.z, rv.z));
    qz.w = __fadd_rn(rv.w, __fsub_rn(qv.w, rv.w));
    rn.x = __fsub_rn(rv.x, qz.x);
    rn.y = __fsub_rn(rv.y, qz.y);
    rn.z = __fsub_rn(rv.z, qz.z);
    rn.w = __fsub_rn(rv.w, qz.w);
    lossAcc = __fadd_rn(lossAcc, __fmul_rn(rn.x, rn.x));
    lossAcc = __fadd_rn(lossAcc, __fmul_rn(rn.y, rn.y));
    lossAcc = __fadd_rn(lossAcc, __fmul_rn(rn.z, rn.z));
    lossAcc = __fadd_rn(lossAcc, __fmul_rn(rn.w, rn.w));
    float4* xqrow = (float4*)(out + (size_t)token * E_DIM);
    if (q == 0) {
        xv = qz;
    } else {
        xv = xqrow[i];
        xv.x = __fadd_rn(xv.x, qz.x);
        xv.y = __fadd_rn(xv.y, qz.y);
        xv.z = __fadd_rn(xv.z, qz.z);
        xv.w = __fadd_rn(xv.w, qz.w);
    }
    xqrow[i] = xv;
    if (q < NUM_Q - 1)
        ((float4*)(g_Rcur + (size_t)token * E_DIM))[i] = rn;
}

// ---------------- kernels ----------------
__global__ void prepA_kernel(const float* __restrict__ cbs) {
    int i = blockIdx.x * blockDim.x + threadIdx.x;
    if (i == 0) {
        g_loss = 0.0;
#pragma unroll
        for (int s = 0; s < NUM_Q; s++) g_ovfcnt[s] = 0;
    }
    if (i >= NUM_Q * KCODES) return;
    const float* row = cbs + (size_t)i * E_DIM;
    float v[E_DIM];
#pragma unroll 8
    for (int e = 0; e < E_DIM; e++) v[e] = __ldg(&row[e]);
    g_cbnorm[i] = rowsumsq_xla_gpu(v);
}
__global__ void prepB_kernel(const float* __restrict__ cbs) {
    int i = blockIdx.x * blockDim.x + threadIdx.x;
    if (i < NUM_Q * KCODES * E_DIM)
        g_Cb[i] = __float2bfloat16(__ldg(&cbs[i]));
}

// Stage kernel: bf16 mma.sync filter ONLY (R11-proven structure).
// Stashes exact Atok to global; finish kernel does rescore + update.
__global__ void __launch_bounds__(256, 2)
stage_kernel(const float* __restrict__ x, int q)
{
    extern __shared__ __align__(16) char smem[];
    const uint32_t sb = smem_u32(smem);
    float* snorm = (float*)(smem + SM_NORM);
    float* sAtok = (float*)(smem + SM_ATOK);
    int*   scnt  = (int*)(smem + SM_CNT);

    const int tid  = threadIdx.x;
    const int wid  = tid >> 5;
    const int lane = tid & 31;
    const int tokBase = blockIdx.x * MTILE;
    const float* Rsrc = (q == 0) ? x : g_Rcur;

    if (tid < MTILE) scnt[tid] = 0;
    for (int i = tid; i < KCODES; i += 256) snorm[i] = g_cbnorm[q * KCODES + i];

    // A tile (bf16(r)) + exact Atok (XLA order)
    if (tid < MTILE) {
        float4 Rr[E_DIM / 4];
        const float4* src = (const float4*)(Rsrc + (size_t)(tokBase + tid) * E_DIM);
#pragma unroll
        for (int i = 0; i < E_DIM / 4; i++) Rr[i] = __ldg(&src[i]);
        sAtok[tid] = rowsumsq_xla_gpu((const float*)Rr);
        __nv_bfloat16* arow = (__nv_bfloat16*)(smem + SM_A + tid * SK_B);
        const float* Rf = (const float*)Rr;
#pragma unroll
        for (int e = 0; e < E_DIM; e++) arow[e] = __float2bfloat16(Rf[e]);
    }
    // prefetch B tile 0
    {
        const char* gB = (const char*)&g_Cb[((size_t)q * KCODES) * E_DIM];
        for (int i = tid; i < NTILE * 16; i += 256)
            CP_ASYNC16(sb + SM_B0 + (i >> 4) * SK_B + (i & 15) * 16,
                       gB + (size_t)i * 16);
        CP_COMMIT();
    }
    __syncthreads();

    const int mBase  = (wid & 3) * 32;    // 4 M-strips of 32 rows
    const int nBaseW = (wid >> 2) * 64;   // 2 N-strips of 64 cols

    float rmin[2][2];
#pragma unroll
    for (int mt = 0; mt < 2; mt++)
        rmin[mt][0] = rmin[mt][1] = __int_as_float(0x7f800000);

    for (int nt = 0; nt < N_NT; nt++) {
        CP_WAIT0();
        __syncthreads();
        if (nt + 1 < N_NT) {
            uint32_t sBn = sb + (((nt + 1) & 1) ? SM_B1 : SM_B0);
            const char* gB = (const char*)
                &g_Cb[((size_t)q * KCODES + (nt + 1) * NTILE) * E_DIM];
            for (int i = tid; i < NTILE * 16; i += 256)
                CP_ASYNC16(sBn + (i >> 4) * SK_B + (i & 15) * 16,
                           gB + (size_t)i * 16);
            CP_COMMIT();
        }
        const uint32_t sBc = sb + ((nt & 1) ? SM_B1 : SM_B0);

        float acc[2][8][4];
#pragma unroll
        for (int mt = 0; mt < 2; mt++)
#pragma unroll
            for (int ng = 0; ng < 8; ng++)
#pragma unroll
                for (int j = 0; j < 4; j++) acc[mt][ng][j] = 0.0f;

        const uint32_t aAddr = sb + SM_A
            + (uint32_t)(mBase + (lane & 15)) * SK_B + (uint32_t)(lane >> 4) * 16;
        const uint32_t bAddr = sBc
            + (uint32_t)(nBaseW + ((lane >> 4) << 3) + (lane & 7)) * SK_B
            + (uint32_t)((lane >> 3) & 1) * 16;

#pragma unroll
        for (int k = 0; k < E_DIM / 16; k++) {
            uint32_t a[2][4];
            LDMATRIX_X4(a[0][0], a[0][1], a[0][2], a[0][3], aAddr + k * 32);
            LDMATRIX_X4(a[1][0], a[1][1], a[1][2], a[1][3],
                        aAddr + 16 * SK_B + k * 32);
            uint32_t b[4][4];
#pragma unroll
            for (int g = 0; g < 4; g++)
                LDMATRIX_X4(b[g][0], b[g][1], b[g][2], b[g][3],
                            bAddr + g * 16 * SK_B + k * 32);
#pragma unroll
            for (int mt = 0; mt < 2; mt++)
#pragma unroll
                for (int g = 0; g < 4; g++) {
                    MMA_BF16(acc[mt][2 * g],     a[mt], b[g][0], b[g][1]);
                    MMA_BF16(acc[mt][2 * g + 1], a[mt], b[g][2], b[g][3]);
                }
        }

        // Epilogue: d-hat, quad-combined tile min -> runmin, margin append
#pragma unroll
        for (int mt = 0; mt < 2; mt++) {
            const int r0 = mBase + mt * 16 + (lane >> 2);
            const int r1 = r0 + 8;
            const float A0 = sAtok[r0], A1 = sAtok[r1];
            float m0 = __int_as_float(0x7f800000), m1 = m0;
#pragma unroll
            for (int ng = 0; ng < 8; ng++) {
                const int c = nt * NTILE + nBaseW + ng * 8 + 2 * (lane & 3);
                const float C0 = snorm[c], C1 = snorm[c + 1];
                float d00 = __fadd_rn(__fsub_rn(A0, __fmul_rn(2.0f, acc[mt][ng][0])), C0);
                float d01 = __fadd_rn(__fsub_rn(A0, __fmul_rn(2.0f, acc[mt][ng][1])), C1);
                float d10 = __fadd_rn(__fsub_rn(A1, __fmul_rn(2.0f, acc[mt][ng][2])), C0);
                float d11 = __fadd_rn(__fsub_rn(A1, __fmul_rn(2.0f, acc[mt][ng][3])), C1);
                acc[mt][ng][0] = d00; acc[mt][ng][1] = d01;
                acc[mt][ng][2] = d10; acc[mt][ng][3] = d11;
                m0 = fminf(m0, fminf(d00, d01));
                m1 = fminf(m1, fminf(d10, d11));
            }
            m0 = fminf(m0, __shfl_xor_sync(0xffffffffu, m0, 1));
            m0 = fminf(m0, __shfl_xor_sync(0xffffffffu, m0, 2));
            m1 = fminf(m1, __shfl_xor_sync(0xffffffffu, m1, 1));
            m1 = fminf(m1, __shfl_xor_sync(0xffffffffu, m1, 2));
            rmin[mt][0] = fminf(rmin[mt][0], m0);
            rmin[mt][1] = fminf(rmin[mt][1], m1);
            const float t0 = rmin[mt][0] + MARGIN;
            const float t1 = rmin[mt][1] + MARGIN;
#pragma unroll
            for (int ng = 0; ng < 8; ng++) {
                const int c = nt * NTILE + nBaseW + ng * 8 + 2 * (lane & 3);
#pragma unroll
                for (int j = 0; j < 4; j++) {
                    const float d = acc[mt][ng][j];
                    const float thr = (j < 2) ? t0 : t1;
                    if (d <= thr) {
                        const int row = (j < 2) ? r0 : r1;
                        int pos = atomicAdd(&scnt[row], 1);
                        if (pos < CAND_CAP)
                            g_cand[(size_t)(tokBase + row) * CAND_CAP + pos] =
                                (unsigned short)(c + (j & 1));
                    }
                }
            }
        }
    }
    __syncthreads();
    if (tid < MTILE) {
        const int token = tokBase + tid;
        g_Atok[token] = sAtok[tid];          // exact A, bit-identical
        int c = scnt[tid];
        if (c > CAND_CAP || c == 0) {
            g_candcnt[token] = 0x80;
            int pos = atomicAdd(&g_ovfcnt[q], 1);
            g_ovftok[q][pos] = token;
        } else {
            g_candcnt[token] = (unsigned char)c;
        }
    }
}

// Finish: slim exact rescore + straight-through. No R register array:
// A comes from g_Atok; r streamed from global in dot_seq / epilogue.
__global__ void __launch_bounds__(256)
finish_stage_kernel(const float* __restrict__ x, const float* __restrict__ cbs,
                    float* __restrict__ out, int q)
{
    const int token = blockIdx.x * 256 + threadIdx.x;
    const unsigned int cc = g_candcnt[token];
    const bool active = !(cc & 0x80u);
    float lossAcc = 0.0f;

    if (active) {
        const float* Rg = ((q == 0) ? x : g_Rcur) + (size_t)token * E_DIM;
        const float* cb = cbs + (size_t)q * KCODES * E_DIM;
        const float A = g_Atok[token];
        float best = __int_as_float(0x7f800000);
        int bestk = 0;
        for (unsigned int i = 0; i < cc; i++) {
            int k = g_cand[(size_t)token * CAND_CAP + i];
            float b = dot_seq(Rg, cb + (size_t)k * E_DIM);
            float dv = __fadd_rn(__fsub_rn(A, __fmul_rn(2.0f, b)),
                                 g_cbnorm[q * KCODES + k]);
            if (i == 0 || dv < best || (dv == best && k < bestk)) {
                best = dv; bestk = k;
            }
        }
        const float4* qrow = (const float4*)(cb + (size_t)bestk * E_DIM);
        const float4* Rg4  = (const float4*)Rg;
#pragma unroll 1
        for (int i = 0; i < E_DIM / 4; i++)
            st_epilogue_elem(token, q, i, __ldg(&Rg4[i]), qrow, out, lossAcc);
        out[(size_t)N_TOKENS * E_DIM + 1 + (size_t)token * NUM_Q + q] =
            (float)bestk;
    }
    // Loss reduction: ALL 32 lanes participate (inactive => 0)
#pragma unroll
    for (int o = 16; o > 0; o >>= 1)
        lossAcc += __shfl_xor_sync(0xffffffffu, lossAcc, o);
    if ((threadIdx.x & 31) == 0 && lossAcc != 0.0f)
        atomicAdd(&g_loss, (double)lossAcc);
}

// Fallback: warp-per-token exact full scan for overflow tokens (rare)
__global__ void __launch_bounds__(256)
fallback_kernel(const float* __restrict__ x, const float* __restrict__ cbs,
                float* __restrict__ out, int q)
{
    __shared__ __align__(16) float sR[8][E_DIM];
    const int cnt   = g_ovfcnt[q];
    const int wslot = threadIdx.x >> 5;
    const int lane  = threadIdx.x & 31;
    const float* cb = cbs + (size_t)q * KCODES * E_DIM;

    for (int qi = blockIdx.x * 8 + wslot; qi < cnt; qi += gridDim.x * 8) {
        const int token = g_ovftok[q][qi];
        const float* Rsrc = (q == 0) ? x : g_Rcur;
        float4 rv = __ldg((const float4*)(Rsrc + (size_t)token * E_DIM) + lane);
        ((float4*)sR[wslot])[lane] = rv;
        __syncwarp();
        float A = rowsumsq_xla_gpu(sR[wslot]);
        float best = __int_as_float(0x7f800000);
        int bestk = KCODES;
#pragma unroll 1
        for (int j = 0; j < KCODES / 32; j++) {
            int k = lane + j * 32;
            float b = dot_seq(sR[wslot], cb + (size_t)k * E_DIM);
            float dv = __fadd_rn(__fsub_rn(A, __fmul_rn(2.0f, b)),
                                 g_cbnorm[q * KCODES + k]);
            if (dv < best || (dv == best && k < bestk)) { best = dv; bestk = k; }
        }
#pragma unroll
        for (int o = 16; o > 0; o >>= 1) {
            float od = __shfl_down_sync(0xffffffffu, best, o);
            int   ok = __shfl_down_sync(0xffffffffu, bestk, o);
            if (od < best || (od == best && ok < bestk)) { best = od; bestk = ok; }
        }
        bestk = __shfl_sync(0xffffffffu, bestk, 0);

        float lossAcc = 0.0f;
        const float4* qrow = (const float4*)(cb + (size_t)bestk * E_DIM);
        st_epilogue_elem(token, q, lane, rv, qrow, out, lossAcc);
#pragma unroll
        for (int o = 16; o > 0; o >>= 1)
            lossAcc += __shfl_xor_sync(0xffffffffu, lossAcc, o);
        if (lane == 0) {
            out[(size_t)N_TOKENS * E_DIM + 1 + (size_t)token * NUM_Q + q] = (float)bestk;
            atomicAdd(&g_loss, (double)lossAcc);
        }
        __syncwarp();
    }
}

__global__ void finalize_loss_kernel(float* __restrict__ out) {
    double v = g_loss * (0.25 / ((double)NUM_Q * (double)N_TOKENS * (double)E_DIM));
    out[(size_t)N_TOKENS * E_DIM] = (float)v;
}

// ---------------- launch ----------------
extern "C" void kernel_launch(void* const* d_in, const int* in_sizes, int n_in,
                              void* d_out, int out_size)
{
    const float* x   = (const float*)d_in[0];   // [131072, 128]
    const float* cbs = (const float*)d_in[1];   // [4, 1024, 128]
    float* out = (float*)d_out;

    cudaFuncSetAttribute(stage_kernel,
                         cudaFuncAttributeMaxDynamicSharedMemorySize, SM_TOTAL);

    prepA_kernel<<<(NUM_Q * KCODES + 127) / 128, 128>>>(cbs);
    prepB_kernel<<<(NUM_Q * KCODES * E_DIM + 255) / 256, 256>>>(cbs);
    for (int q = 0; q < NUM_Q; q++) {
        stage_kernel<<<N_TOKENS / MTILE, 256, SM_TOTAL>>>(x, q);
        finish_stage_kernel<<<N_TOKENS / 256, 256>>>(x, cbs, out, q);
        fallback_kernel<<<128, 256>>>(x, cbs, out, q);
    }
    finalize_loss_kernel<<<1, 1>>>(out);
}

// round 15
// speedup vs baseline: 7.2369x; 7.0983x over previous
#include <cuda_runtime.h>
#include <cuda_bf16.h>
#include <math.h>
#include <stdint.h>

// Problem constants
#define N_TOKENS 131072
#define E_DIM    128
#define KCODES   1024
#define NUM_Q    4
#define MTILE    128                 // tokens per CTA
#define NTILE    128                 // codes per N-tile
#define N_NT     (KCODES / NTILE)    // 8
#define CAND_CAP 8
#define MARGIN   1.5e-3f
#define SK_B     272                 // smem row stride bytes (128 bf16 + 16B pad)

// SMEM byte offsets (R11-proven layout)
#define SM_A     0                   // 128*272 = 34816
#define SM_B0    34816
#define SM_B1    69632
#define SM_NORM  104448              // 1024 f32
#define SM_ATOK  108544              // 128 f32
#define SM_RMIN  109056              // 128 f32
#define SM_CNT   109568              // 128 i32
#define SM_TOTAL 110080              // 107.5 KB -> 2 CTAs/SM

// ---------------- device globals (no allocations allowed) ----------------
__device__ double g_loss;
__device__ float  g_cbnorm[NUM_Q * KCODES];
__device__ float  g_Atok[N_TOKENS];                              // exact A per token
__device__ float  g_Rcur[(size_t)N_TOKENS * E_DIM];
__device__ __nv_bfloat16 g_Cb[(size_t)NUM_Q * KCODES * E_DIM];   // bf16(cb)
__device__ unsigned short g_cand[(size_t)N_TOKENS * CAND_CAP];
__device__ unsigned char  g_candcnt[N_TOKENS];
__device__ int g_ovfcnt[NUM_Q];
__device__ int g_ovftok[NUM_Q][N_TOKENS];

// ---------------- PTX helpers (sm_80+-portable; no tcgen05!) ----------------
__device__ __forceinline__ uint32_t smem_u32(const void* p) {
    uint32_t a;
    asm("{ .reg .u64 t; cvta.to.shared.u64 t, %1; cvt.u32.u64 %0, t; }"
        : "=r"(a) : "l"(p));
    return a;
}
#define CP_ASYNC16(sa, ga) \
    asm volatile("cp.async.cg.shared.global [%0], [%1], 16;" :: "r"(sa), "l"(ga))
#define CP_COMMIT() asm volatile("cp.async.commit_group;" ::: "memory")
#define CP_WAIT0()  asm volatile("cp.async.wait_group 0;" ::: "memory")
#define LDMATRIX_X4(r0, r1, r2, r3, addr) \
    asm volatile("ldmatrix.sync.aligned.m8n8.x4.shared.b16 {%0,%1,%2,%3}, [%4];" \
                 : "=r"(r0), "=r"(r1), "=r"(r2), "=r"(r3) : "r"(addr))
#define MMA_BF16(c, a, b0v, b1v) \
    asm volatile("mma.sync.aligned.m16n8k16.row.col.f32.bf16.bf16.f32 " \
                 "{%0,%1,%2,%3}, {%4,%5,%6,%7}, {%8,%9}, {%0,%1,%2,%3};" \
                 : "+f"((c)[0]), "+f"((c)[1]), "+f"((c)[2]), "+f"((c)[3]) \
                 : "r"((a)[0]), "r"((a)[1]), "r"((a)[2]), "r"((a)[3]), \
                   "r"(b0v), "r"(b1v))

__device__ __forceinline__ void atomicMinF(float* p, float v) {
    atomicMin((int*)p, __float_as_int(v));   // valid for positive floats
}

// ---------------- proven numeric contracts (DO NOT TOUCH) ----------------
__device__ __forceinline__ float rowsumsq_xla_gpu(const float* v) {
    float part[32];
#pragma unroll
    for (int l = 0; l < 32; l++) {
        float a = __fmul_rn(v[l], v[l]);
        a = __fadd_rn(a, __fmul_rn(v[l + 32], v[l + 32]));
        a = __fadd_rn(a, __fmul_rn(v[l + 64], v[l + 64]));
        a = __fadd_rn(a, __fmul_rn(v[l + 96], v[l + 96]));
        part[l] = a;
    }
#pragma unroll
    for (int off = 16; off > 0; off >>= 1)
#pragma unroll
        for (int l = 0; l < 16; l++)
            if (l < off) part[l] = __fadd_rn(part[l], part[l + off]);
    return part[0];
}
// Exact B dot: sequential fused FMA ascending e; r via plain generic loads
// (valid for global OR shared pointers); cb always global -> __ldg.
__device__ __forceinline__ float dot_seq(const float* __restrict__ r,
                                         const float* __restrict__ cb) {
    float acc = 0.0f;
#pragma unroll
    for (int i = 0; i < E_DIM / 4; i++) {
        float4 c = __ldg((const float4*)cb + i);
        float4 rv = ((const float4*)r)[i];
        acc = fmaf(rv.x, c.x, acc);
        acc = fmaf(rv.y, c.y, acc);
        acc = fmaf(rv.z, c.z, acc);
        acc = fmaf(rv.w, c.w, acc);
    }
    return acc;
}

// Straight-through epilogue for one float4 block (proven bit-exact path)
__device__ __forceinline__ void st_epilogue_elem(
    int token, int q, int i, float4 rv, const float4* qrow,
    float* out, float& lossAcc)
{
    float4 qv = __ldg(&qrow[i]);
    float4 qz, rn, xv;
    qz.x = __fadd_rn(rv.x, __fsub_rn(qv.x, rv.x));
    qz.y = __fadd_rn(rv.y, __fsub_rn(qv.y, rv.y));
    qz.z = __fadd_rn(rv.z, __fsub_rn(qv.z, rv.z));
    qz.w = __fadd_rn(rv.w, __fsub_rn(qv.w, rv.w));
    rn.x = __fsub_rn(rv.x, qz.x);
    rn.y = __fsub_rn(rv.y, qz.y);
    rn.z = __fsub_rn(rv.z, qz.z);
    rn.w = __fsub_rn(rv.w, qz.w);
    lossAcc = __fadd_rn(lossAcc, __fmul_rn(rn.x, rn.x));
    lossAcc = __fadd_rn(lossAcc, __fmul_rn(rn.y, rn.y));
    lossAcc = __fadd_rn(lossAcc, __fmul_rn(rn.z, rn.z));
    lossAcc = __fadd_rn(lossAcc, __fmul_rn(rn.w, rn.w));
    float4* xqrow = (float4*)(out + (size_t)token * E_DIM);
    if (q == 0) {
        xv = qz;
    } else {
        xv = xqrow[i];
        xv.x = __fadd_rn(xv.x, qz.x);
        xv.y = __fadd_rn(xv.y, qz.y);
        xv.z = __fadd_rn(xv.z, qz.z);
        xv.w = __fadd_rn(xv.w, qz.w);
    }
    xqrow[i] = xv;
    if (q < NUM_Q - 1)
        ((float4*)(g_Rcur + (size_t)token * E_DIM))[i] = rn;
}

// ---------------- kernels ----------------
__global__ void prepA_kernel(const float* __restrict__ cbs) {
    int i = blockIdx.x * blockDim.x + threadIdx.x;
    if (i == 0) {
        g_loss = 0.0;
#pragma unroll
        for (int s = 0; s < NUM_Q; s++) g_ovfcnt[s] = 0;
    }
    if (i >= NUM_Q * KCODES) return;
    const float* row = cbs + (size_t)i * E_DIM;
    float v[E_DIM];
#pragma unroll 8
    for (int e = 0; e < E_DIM; e++) v[e] = __ldg(&row[e]);
    g_cbnorm[i] = rowsumsq_xla_gpu(v);
}
__global__ void prepB_kernel(const float* __restrict__ cbs) {
    int i = blockIdx.x * blockDim.x + threadIdx.x;
    if (i < NUM_Q * KCODES * E_DIM)
        g_Cb[i] = __float2bfloat16(__ldg(&cbs[i]));
}

// GEMM filter: EXACT R11-bench structure (srmin smem, two-phase epilogue).
// Only addition: g_Atok store in the tail (outside all loops).
__global__ void __launch_bounds__(256, 2)
gemm_stage_kernel(const float* __restrict__ x, int q)
{
    extern __shared__ __align__(16) char smem[];
    const uint32_t sb = smem_u32(smem);
    float* snorm = (float*)(smem + SM_NORM);
    float* sAtok = (float*)(smem + SM_ATOK);
    float* srmin = (float*)(smem + SM_RMIN);
    int*   scnt  = (int*)(smem + SM_CNT);

    const int tid  = threadIdx.x;
    const int wid  = tid >> 5;
    const int lane = tid & 31;
    const int tokBase = blockIdx.x * MTILE;
    const float* Rsrc = (q == 0) ? x : g_Rcur;

    if (tid < MTILE) { scnt[tid] = 0; srmin[tid] = __int_as_float(0x7f800000); }
    for (int i = tid; i < KCODES; i += 256) snorm[i] = g_cbnorm[q * KCODES + i];

    // A tile (bf16(r)) + exact Atok (XLA order)
    if (tid < MTILE) {
        float4 Rr[E_DIM / 4];
        const float4* src = (const float4*)(Rsrc + (size_t)(tokBase + tid) * E_DIM);
#pragma unroll
        for (int i = 0; i < E_DIM / 4; i++) Rr[i] = __ldg(&src[i]);
        sAtok[tid] = rowsumsq_xla_gpu((const float*)Rr);
        __nv_bfloat16* arow = (__nv_bfloat16*)(smem + SM_A + tid * SK_B);
        const float* Rf = (const float*)Rr;
#pragma unroll
        for (int e = 0; e < E_DIM; e++) arow[e] = __float2bfloat16(Rf[e]);
    }
    // prefetch B tile 0
    {
        const char* gB = (const char*)&g_Cb[((size_t)q * KCODES) * E_DIM];
        for (int i = tid; i < NTILE * 16; i += 256)
            CP_ASYNC16(sb + SM_B0 + (i >> 4) * SK_B + (i & 15) * 16,
                       gB + (size_t)i * 16);
        CP_COMMIT();
    }
    __syncthreads();

    const int mBase  = (wid & 3) * 32;    // 4 M-strips of 32 rows
    const int nBaseW = (wid >> 2) * 64;   // 2 N-strips of 64 cols

    for (int nt = 0; nt < N_NT; nt++) {
        CP_WAIT0();
        __syncthreads();
        if (nt + 1 < N_NT) {
            uint32_t sBn = sb + (((nt + 1) & 1) ? SM_B1 : SM_B0);
            const char* gB = (const char*)
                &g_Cb[((size_t)q * KCODES + (nt + 1) * NTILE) * E_DIM];
            for (int i = tid; i < NTILE * 16; i += 256)
                CP_ASYNC16(sBn + (i >> 4) * SK_B + (i & 15) * 16,
                           gB + (size_t)i * 16);
            CP_COMMIT();
        }
        const uint32_t sBc = sb + ((nt & 1) ? SM_B1 : SM_B0);

        float acc[2][8][4];
#pragma unroll
        for (int mt = 0; mt < 2; mt++)
#pragma unroll
            for (int ng = 0; ng < 8; ng++)
#pragma unroll
                for (int j = 0; j < 4; j++) acc[mt][ng][j] = 0.0f;

        const uint32_t aAddr = sb + SM_A
            + (uint32_t)(mBase + (lane & 15)) * SK_B + (uint32_t)(lane >> 4) * 16;
        const uint32_t bAddr = sBc
            + (uint32_t)(nBaseW + ((lane >> 4) << 3) + (lane & 7)) * SK_B
            + (uint32_t)((lane >> 3) & 1) * 16;

#pragma unroll
        for (int k = 0; k < E_DIM / 16; k++) {
            uint32_t a[2][4];
            LDMATRIX_X4(a[0][0], a[0][1], a[0][2], a[0][3], aAddr + k * 32);
            LDMATRIX_X4(a[1][0], a[1][1], a[1][2], a[1][3],
                        aAddr + 16 * SK_B + k * 32);
            uint32_t b[4][4];
#pragma unroll
            for (int g = 0; g < 4; g++)
                LDMATRIX_X4(b[g][0], b[g][1], b[g][2], b[g][3],
                            bAddr + g * 16 * SK_B + k * 32);
#pragma unroll
            for (int mt = 0; mt < 2; mt++)
#pragma unroll
                for (int g = 0; g < 4; g++) {
                    MMA_BF16(acc[mt][2 * g],     a[mt], b[g][0], b[g][1]);
                    MMA_BF16(acc[mt][2 * g + 1], a[mt], b[g][2], b[g][3]);
                }
        }

        // Epilogue phase 1: d-hat + row running-min (smem srmin, R11-proven)
#pragma unroll
        for (int mt = 0; mt < 2; mt++) {
            const int r0 = mBase + mt * 16 + (lane >> 2);
            const int r1 = r0 + 8;
            const float A0 = sAtok[r0], A1 = sAtok[r1];
            float m0 = __int_as_float(0x7f800000), m1 = m0;
#pragma unroll
            for (int ng = 0; ng < 8; ng++) {
                const int c = nt * NTILE + nBaseW + ng * 8 + 2 * (lane & 3);
                const float C0 = snorm[c], C1 = snorm[c + 1];
                float d00 = __fadd_rn(__fsub_rn(A0, __fmul_rn(2.0f, acc[mt][ng][0])), C0);
                float d01 = __fadd_rn(__fsub_rn(A0, __fmul_rn(2.0f, acc[mt][ng][1])), C1);
                float d10 = __fadd_rn(__fsub_rn(A1, __fmul_rn(2.0f, acc[mt][ng][2])), C0);
                float d11 = __fadd_rn(__fsub_rn(A1, __fmul_rn(2.0f, acc[mt][ng][3])), C1);
                acc[mt][ng][0] = d00; acc[mt][ng][1] = d01;
                acc[mt][ng][2] = d10; acc[mt][ng][3] = d11;
                m0 = fminf(m0, fminf(d00, d01));
                m1 = fminf(m1, fminf(d10, d11));
            }
            m0 = fminf(m0, __shfl_xor_sync(0xffffffffu, m0, 1));
            m0 = fminf(m0, __shfl_xor_sync(0xffffffffu, m0, 2));
            m1 = fminf(m1, __shfl_xor_sync(0xffffffffu, m1, 1));
            m1 = fminf(m1, __shfl_xor_sync(0xffffffffu, m1, 2));
            if ((lane & 3) == 0) { atomicMinF(&srmin[r0], m0); atomicMinF(&srmin[r1], m1); }
        }
        __syncthreads();
        // Phase 2: margin append (srmin >= true row min at all times => sound)
#pragma unroll
        for (int mt = 0; mt < 2; mt++) {
            const int r0 = mBase + mt * 16 + (lane >> 2);
            const int r1 = r0 + 8;
            const float t0 = srmin[r0] + MARGIN;
            const float t1 = srmin[r1] + MARGIN;
#pragma unroll
            for (int ng = 0; ng < 8; ng++) {
                const int c = nt * NTILE + nBaseW + ng * 8 + 2 * (lane & 3);
#pragma unroll
                for (int j = 0; j < 4; j++) {
                    const float d = acc[mt][ng][j];
                    const float thr = (j < 2) ? t0 : t1;
                    if (d <= thr) {
                        const int row = (j < 2) ? r0 : r1;
                        int pos = atomicAdd(&scnt[row], 1);
                        if (pos < CAND_CAP)
                            g_cand[(size_t)(tokBase + row) * CAND_CAP + pos] =
                                (unsigned short)(c + (j & 1));
                    }
                }
            }
        }
    }
    __syncthreads();
    if (tid < MTILE) {
        const int token = tokBase + tid;
        g_Atok[token] = sAtok[tid];          // exact A, bit-identical
        int c = scnt[tid];
        if (c > CAND_CAP || c == 0) {
            g_candcnt[token] = 0x80;
            int pos = atomicAdd(&g_ovfcnt[q], 1);
            g_ovftok[q][pos] = token;
        } else {
            g_candcnt[token] = (unsigned char)c;
        }
    }
}

// Finish: slim exact rescore + straight-through (A from g_Atok, r streamed)
__global__ void __launch_bounds__(256)
finish_stage_kernel(const float* __restrict__ x, const float* __restrict__ cbs,
                    float* __restrict__ out, int q)
{
    const int token = blockIdx.x * 256 + threadIdx.x;
    const unsigned int cc = g_candcnt[token];
    const bool active = !(cc & 0x80u);
    float lossAcc = 0.0f;

    if (active) {
        const float* Rg = ((q == 0) ? x : g_Rcur) + (size_t)token * E_DIM;
        const float* cb = cbs + (size_t)q * KCODES * E_DIM;
        const float A = g_Atok[token];
        float best = __int_as_float(0x7f800000);
        int bestk = 0;
        for (unsigned int i = 0; i < cc; i++) {
            int k = g_cand[(size_t)token * CAND_CAP + i];
            float b = dot_seq(Rg, cb + (size_t)k * E_DIM);
            float dv = __fadd_rn(__fsub_rn(A, __fmul_rn(2.0f, b)),
                                 g_cbnorm[q * KCODES + k]);
            if (i == 0 || dv < best || (dv == best && k < bestk)) {
                best = dv; bestk = k;
            }
        }
        const float4* qrow = (const float4*)(cb + (size_t)bestk * E_DIM);
        const float4* Rg4  = (const float4*)Rg;
#pragma unroll 1
        for (int i = 0; i < E_DIM / 4; i++)
            st_epilogue_elem(token, q, i, __ldg(&Rg4[i]), qrow, out, lossAcc);
        out[(size_t)N_TOKENS * E_DIM + 1 + (size_t)token * NUM_Q + q] =
            (float)bestk;
    }
    // Loss reduction: ALL 32 lanes participate (inactive => 0)
#pragma unroll
    for (int o = 16; o > 0; o >>= 1)
        lossAcc += __shfl_xor_sync(0xffffffffu, lossAcc, o);
    if ((threadIdx.x & 31) == 0 && lossAcc != 0.0f)
        atomicAdd(&g_loss, (double)lossAcc);
}

// Fallback: warp-per-token exact full scan for overflow tokens (rare)
__global__ void __launch_bounds__(256)
fallback_kernel(const float* __restrict__ x, const float* __restrict__ cbs,
                float* __restrict__ out, int q)
{
    __shared__ __align__(16) float sR[8][E_DIM];
    const int cnt   = g_ovfcnt[q];
    const int wslot = threadIdx.x >> 5;
    const int lane  = threadIdx.x & 31;
    const float* cb = cbs + (size_t)q * KCODES * E_DIM;

    for (int qi = blockIdx.x * 8 + wslot; qi < cnt; qi += gridDim.x * 8) {
        const int token = g_ovftok[q][qi];
        const float* Rsrc = (q == 0) ? x : g_Rcur;
        float4 rv = __ldg((const float4*)(Rsrc + (size_t)token * E_DIM) + lane);
        ((float4*)sR[wslot])[lane] = rv;
        __syncwarp();
        float A = rowsumsq_xla_gpu(sR[wslot]);
        float best = __int_as_float(0x7f800000);
        int bestk = KCODES;
#pragma unroll 1
        for (int j = 0; j < KCODES / 32; j++) {
            int k = lane + j * 32;
            float b = dot_seq(sR[wslot], cb + (size_t)k * E_DIM);
            float dv = __fadd_rn(__fsub_rn(A, __fmul_rn(2.0f, b)),
                                 g_cbnorm[q * KCODES + k]);
            if (dv < best || (dv == best && k < bestk)) { best = dv; bestk = k; }
        }
#pragma unroll
        for (int o = 16; o > 0; o >>= 1) {
            float od = __shfl_down_sync(0xffffffffu, best, o);
            int   ok = __shfl_down_sync(0xffffffffu, bestk, o);
            if (od < best || (od == best && ok < bestk)) { best = od; bestk = ok; }
        }
        bestk = __shfl_sync(0xffffffffu, bestk, 0);

        float lossAcc = 0.0f;
        const float4* qrow = (const float4*)(cb + (size_t)bestk * E_DIM);
        st_epilogue_elem(token, q, lane, rv, qrow, out, lossAcc);
#pragma unroll
        for (int o = 16; o > 0; o >>= 1)
            lossAcc += __shfl_xor_sync(0xffffffffu, lossAcc, o);
        if (lane == 0) {
            out[(size_t)N_TOKENS * E_DIM + 1 + (size_t)token * NUM_Q + q] = (float)bestk;
            atomicAdd(&g_loss, (double)lossAcc);
        }
        __syncwarp();
    }
}

__global__ void finalize_loss_kernel(float* __restrict__ out) {
    double v = g_loss * (0.25 / ((double)NUM_Q * (double)N_TOKENS * (double)E_DIM));
    out[(size_t)N_TOKENS * E_DIM] = (float)v;
}

// ---------------- launch ----------------
extern "C" void kernel_launch(void* const* d_in, const int* in_sizes, int n_in,
                              void* d_out, int out_size)
{
    const float* x   = (const float*)d_in[0];   // [131072, 128]
    const float* cbs = (const float*)d_in[1];   // [4, 1024, 128]
    float* out = (float*)d_out;

    cudaFuncSetAttribute(gemm_stage_kernel,
                         cudaFuncAttributeMaxDynamicSharedMemorySize, SM_TOTAL);

    prepA_kernel<<<(NUM_Q * KCODES + 127) / 128, 128>>>(cbs);
    prepB_kernel<<<(NUM_Q * KCODES * E_DIM + 255) / 256, 256>>>(cbs);
    for (int q = 0; q < NUM_Q; q++) {
        gemm_stage_kernel<<<N_TOKENS / MTILE, 256, SM_TOTAL>>>(x, q);
        finish_stage_kernel<<<N_TOKENS / 256, 256>>>(x, cbs, out, q);
        fallback_kernel<<<128, 256>>>(x, cbs, out, q);
    }
    finalize_loss_kernel<<<1, 1>>>(out);
}